// round 15
// baseline (speedup 1.0000x reference)
#include <cuda_runtime.h>
#include <cuda_fp16.h>
#include <math.h>
#include <stdint.h>

// Problem constants
#define BATCH 2
#define TSEQ  1024
#define DIMM  512
#define NHEAD 8
#define DKH   64
#define NROWS (BATCH * TSEQ)   // 2048

// ---------------------------------------------------------------------------
// Scratch (__device__ globals) — everything single fp16
// ---------------------------------------------------------------------------
__device__ __align__(16) float  g_G[NROWS * DIMM];
__device__ __align__(16) __half g_Xh[NROWS * DIMM];     // x
__device__ __align__(16) __half g_Qx[NROWS * DIMM];     // Q
__device__ __align__(16) __half g_Kx[NROWS * DIMM];     // K
__device__ __align__(16) __half g_Vtx[NROWS * DIMM];    // V transposed [(b*8+h)*64+d][t]
__device__ __align__(16) __half g_Ox[NROWS * DIMM];     // gated O
__device__ __align__(16) __half g_Ws[5 * DIMM * DIMM];  // Wq,Wk,Wv,Wg,Wo ^T [n][k]

// ---------------------------------------------------------------------------
// helpers
// ---------------------------------------------------------------------------
__device__ __forceinline__ uint32_t smem_u32(const void* p) {
    uint32_t a;
    asm("{ .reg .u64 t; cvta.to.shared.u64 t, %1; cvt.u32.u64 %0, t; }" : "=r"(a) : "l"(p));
    return a;
}
__device__ __forceinline__ void cp_async16(uint32_t dst, const void* src) {
    asm volatile("cp.async.cg.shared.global [%0], [%1], 16;" :: "r"(dst), "l"(src));
}
__device__ __forceinline__ void cp_commit() {
    asm volatile("cp.async.commit_group;" ::: "memory");
}
template <int N>
__device__ __forceinline__ void cp_wait() {
    asm volatile("cp.async.wait_group %0;" :: "n"(N) : "memory");
}
__device__ __forceinline__ void ldsm4(uint32_t* r, uint32_t addr) {
    asm volatile("ldmatrix.sync.aligned.m8n8.x4.shared.b16 {%0,%1,%2,%3}, [%4];"
        : "=r"(r[0]), "=r"(r[1]), "=r"(r[2]), "=r"(r[3]) : "r"(addr));
}
__device__ __forceinline__ void mma16816(float* c,
                                         uint32_t a0, uint32_t a1, uint32_t a2, uint32_t a3,
                                         uint32_t b0, uint32_t b1) {
    asm volatile(
        "mma.sync.aligned.m16n8k16.row.col.f32.f16.f16.f32 "
        "{%0,%1,%2,%3}, {%4,%5,%6,%7}, {%8,%9}, {%0,%1,%2,%3};"
        : "+f"(c[0]), "+f"(c[1]), "+f"(c[2]), "+f"(c[3])
        : "r"(a0), "r"(a1), "r"(a2), "r"(a3), "r"(b0), "r"(b1));
}
__device__ __forceinline__ uint32_t f22h2(float a, float b) {
    __half2 t = __float22half2_rn(make_float2(a, b));
    return *(uint32_t*)&t;
}

// ---------------------------------------------------------------------------
// prep: z<5 -> weight transpose -> fp16 single; z>=5 -> x -> fp16
// ---------------------------------------------------------------------------
__global__ void __launch_bounds__(256) prep_kernel(
    const float* __restrict__ x,
    const float* __restrict__ Wq, const float* __restrict__ Wk,
    const float* __restrict__ Wv, const float* __restrict__ Wg,
    const float* __restrict__ Wo)
{
    if (blockIdx.z < 5) {
        __shared__ float t[32][33];
        const int w = blockIdx.z;
        const float* __restrict__ W = (w == 0) ? Wq : (w == 1) ? Wk : (w == 2) ? Wv : (w == 3) ? Wg : Wo;
        __half* Ws = g_Ws + (size_t)w * DIMM * DIMM;

        const int tx = threadIdx.x & 31, ty = threadIdx.x >> 5;
        const int n0 = blockIdx.x * 32, k0 = blockIdx.y * 32;
#pragma unroll
        for (int j = 0; j < 4; j++)
            t[ty + 8 * j][tx] = W[(size_t)(k0 + ty + 8 * j) * DIMM + n0 + tx];
        __syncthreads();
#pragma unroll
        for (int j = 0; j < 4; j++) {
            float v = t[tx][ty + 8 * j];
            size_t o = (size_t)(n0 + ty + 8 * j) * DIMM + k0 + tx;
            Ws[o] = __float2half(v);
        }
    } else {
        int bid = (blockIdx.z - 5) * 256 + blockIdx.y * 16 + blockIdx.x;
        int i4 = (bid * 256 + threadIdx.x) * 4;
        float4 v = *(const float4*)(x + i4);
        *(__half2*)(g_Xh + i4)     = __float22half2_rn(make_float2(v.x, v.y));
        *(__half2*)(g_Xh + i4 + 2) = __float22half2_rn(make_float2(v.z, v.w));
    }
}

// ---------------------------------------------------------------------------
// Proj GEMM: 64x128 tile, K=512, chunk 32, 4-stage, 256 threads (R12 proven)
// MODE 2: transposed V single; 3: sigmoid+bias float; 4: relu single
// ---------------------------------------------------------------------------
#define PADK 40
#define BUFA_B (64 * PADK * 2)          // 5120 bytes
#define BUFB_B (128 * PADK * 2)         // 10240 bytes
#define STAGE_B (BUFA_B + BUFB_B)       // 15360
#define GEMM_SMEM_BYTES (4 * STAGE_B)   // 61440

template<int MODE>
__device__ __forceinline__ void proj_gemm_tile(
    const __half* __restrict__ A0, const __half* __restrict__ B0,
    int m0, int n0,
    float* __restrict__ fout, __half* __restrict__ o1,
    const float* __restrict__ bias)
{
    extern __shared__ __half sm[];
    const uint32_t smb = smem_u32(sm);

    const int tid = threadIdx.x;
    const int wid = tid >> 5;
    const int lane = tid & 31;
    const int wm = wid >> 2;
    const int wn = wid & 3;
    const int gid = lane >> 2;
    const int qid = lane & 3;

    const uint32_t a_off = (uint32_t)((wm * 32 + (lane & 15)) * PADK + (lane >> 4) * 8) * 2;
    const uint32_t b_off = (uint32_t)((wn * 32 + (lane & 7)) * PADK + (lane >> 3) * 8) * 2;

    float c[2][4][4];
#pragma unroll
    for (int i = 0; i < 2; i++)
#pragma unroll
        for (int j = 0; j < 4; j++)
#pragma unroll
            for (int k = 0; k < 4; k++) c[i][j][k] = 0.f;

    auto prefetch = [&](int chunk, int stage) {
        const int k0 = chunk * 32;
        const uint32_t sbase = smb + (uint32_t)stage * STAGE_B;
        {
            int row = tid >> 2, seg = tid & 3;
            cp_async16(sbase + (uint32_t)(row * PADK + seg * 8) * 2,
                       A0 + (size_t)(m0 + row) * DIMM + k0 + seg * 8);
        }
#pragma unroll
        for (int t = 0; t < 2; t++) {
            int id = tid + t * 256;
            int row = id >> 2, seg = id & 3;
            cp_async16(sbase + BUFA_B + (uint32_t)(row * PADK + seg * 8) * 2,
                       B0 + (size_t)(n0 + row) * DIMM + k0 + seg * 8);
        }
        cp_commit();
    };

    prefetch(0, 0);
    prefetch(1, 1);
    prefetch(2, 2);

    for (int chunk = 0; chunk < 16; chunk++) {
        const int stage = chunk & 3;
        if (chunk + 3 < 16) prefetch(chunk + 3, (chunk + 3) & 3);
        else cp_commit();
        cp_wait<3>();
        __syncthreads();

        const uint32_t s0 = smb + (uint32_t)stage * STAGE_B;

        uint32_t bf[4][4];
#pragma unroll
        for (int nf = 0; nf < 4; nf++)
            ldsm4(bf[nf], s0 + BUFA_B + b_off + (uint32_t)nf * (8 * PADK * 2));

#pragma unroll
        for (int ks = 0; ks < 2; ks++) {
            uint32_t af[2][4];
#pragma unroll
            for (int mf = 0; mf < 2; mf++)
                ldsm4(af[mf], s0 + a_off + (uint32_t)mf * (16 * PADK * 2) + (uint32_t)ks * 32);
#pragma unroll
            for (int nf = 0; nf < 4; nf++) {
                const uint32_t p0 = bf[nf][ks * 2], p1 = bf[nf][ks * 2 + 1];
#pragma unroll
                for (int mf = 0; mf < 2; mf++)
                    mma16816(c[mf][nf], af[mf][0], af[mf][1], af[mf][2], af[mf][3], p0, p1);
            }
        }
        __syncthreads();
    }

#pragma unroll
    for (int mf = 0; mf < 2; mf++) {
#pragma unroll
        for (int nf = 0; nf < 4; nf++) {
            int m = m0 + wm * 32 + mf * 16 + gid;
            int n = n0 + wn * 32 + nf * 8 + qid * 2;
            float v0 = c[mf][nf][0], v1 = c[mf][nf][1];
            float v2 = c[mf][nf][2], v3 = c[mf][nf][3];
            if (MODE == 2) {
                int bb = m >> 10, tt = m & 1023;
                int hh = n >> 6, dd = n & 63;
                size_t base = ((size_t)((bb * 8 + hh) * 64 + dd)) * 1024 + tt;
                o1[base]        = __float2half(v0);
                o1[base + 1024] = __float2half(v1);
                o1[base + 8]    = __float2half(v2);
                o1[base + 1032] = __float2half(v3);
            } else if (MODE == 3) {
                float b0 = bias[n], b1v = bias[n + 1];
                v0 = 1.f / (1.f + expf(-(v0 + b0)));
                v1 = 1.f / (1.f + expf(-(v1 + b1v)));
                v2 = 1.f / (1.f + expf(-(v2 + b0)));
                v3 = 1.f / (1.f + expf(-(v3 + b1v)));
                *(float2*)(fout + (size_t)m * DIMM + n)       = make_float2(v0, v1);
                *(float2*)(fout + (size_t)(m + 8) * DIMM + n) = make_float2(v2, v3);
            } else { // MODE 4: relu -> single fp16
                v0 = fmaxf(v0, 0.f); v1 = fmaxf(v1, 0.f);
                v2 = fmaxf(v2, 0.f); v3 = fmaxf(v3, 0.f);
                *(uint32_t*)(o1 + (size_t)m * DIMM + n)       = f22h2(v0, v1);
                *(uint32_t*)(o1 + (size_t)(m + 8) * DIMM + n) = f22h2(v2, v3);
            }
        }
    }
}

__global__ void __launch_bounds__(256) mma_proj_kernel(const float* __restrict__ bg)
{
    const int zi = blockIdx.z;
    const int m0 = blockIdx.y * 64, n0 = blockIdx.x * 128;
    if (zi == 0)
        proj_gemm_tile<4>(g_Xh, g_Ws + 0 * DIMM * DIMM, m0, n0, nullptr, g_Qx, nullptr);
    else if (zi == 1)
        proj_gemm_tile<4>(g_Xh, g_Ws + 1 * DIMM * DIMM, m0, n0, nullptr, g_Kx, nullptr);
    else if (zi == 2)
        proj_gemm_tile<2>(g_Xh, g_Ws + 2 * DIMM * DIMM, m0, n0, nullptr, g_Vtx, nullptr);
    else
        proj_gemm_tile<3>(g_Xh, g_Ws + 3 * DIMM * DIMM, m0, n0, g_G, nullptr, bg);
}

// ---------------------------------------------------------------------------
// Out GEMM: 64x128 tile, K=512, chunk 32, 4-stage, 512 THREADS (16 warps,
// 4m x 4n, warp tile 16x32) — doubles warps/SM on the grid=128 launch.
// ---------------------------------------------------------------------------
__global__ void __launch_bounds__(512) mma_out_kernel(float* __restrict__ out)
{
    extern __shared__ __half sm[];
    const uint32_t smb = smem_u32(sm);
    const __half* __restrict__ A0 = g_Ox;
    const __half* __restrict__ B0 = g_Ws + 4 * DIMM * DIMM;
    const int m0 = blockIdx.y * 64, n0 = blockIdx.x * 128;

    const int tid = threadIdx.x;
    const int wid = tid >> 5;          // 0..15
    const int lane = tid & 31;
    const int wm = wid >> 2;           // 0..3 (16-row slice)
    const int wn = wid & 3;            // 0..3 (32-col quarter)
    const int gid = lane >> 2;
    const int qid = lane & 3;

    const uint32_t a_off = (uint32_t)((wm * 16 + (lane & 15)) * PADK + (lane >> 4) * 8) * 2;
    const uint32_t b_off = (uint32_t)((wn * 32 + (lane & 7)) * PADK + (lane >> 3) * 8) * 2;

    float c[4][4];
#pragma unroll
    for (int j = 0; j < 4; j++)
#pragma unroll
        for (int k = 0; k < 4; k++) c[j][k] = 0.f;

    auto prefetch = [&](int chunk, int stage) {
        const int k0 = chunk * 32;
        const uint32_t sbase = smb + (uint32_t)stage * STAGE_B;
        // A: 64 rows x 32 cols = 256 16B loads (first 256 threads)
        if (tid < 256) {
            int row = tid >> 2, seg = tid & 3;
            cp_async16(sbase + (uint32_t)(row * PADK + seg * 8) * 2,
                       A0 + (size_t)(m0 + row) * DIMM + k0 + seg * 8);
        }
        // B: 128 rows x 32 cols = 512 16B loads (1 per thread)
        {
            int row = tid >> 2, seg = tid & 3;
            cp_async16(sbase + BUFA_B + (uint32_t)(row * PADK + seg * 8) * 2,
                       B0 + (size_t)(n0 + row) * DIMM + k0 + seg * 8);
        }
        cp_commit();
    };

    prefetch(0, 0);
    prefetch(1, 1);
    prefetch(2, 2);

    for (int chunk = 0; chunk < 16; chunk++) {
        const int stage = chunk & 3;
        if (chunk + 3 < 16) prefetch(chunk + 3, (chunk + 3) & 3);
        else cp_commit();
        cp_wait<3>();
        __syncthreads();

        const uint32_t s0 = smb + (uint32_t)stage * STAGE_B;

        uint32_t bf[4][4];
#pragma unroll
        for (int nf = 0; nf < 4; nf++)
            ldsm4(bf[nf], s0 + BUFA_B + b_off + (uint32_t)nf * (8 * PADK * 2));

#pragma unroll
        for (int ks = 0; ks < 2; ks++) {
            uint32_t af[4];
            ldsm4(af, s0 + a_off + (uint32_t)ks * 32);
#pragma unroll
            for (int nf = 0; nf < 4; nf++)
                mma16816(c[nf], af[0], af[1], af[2], af[3],
                         bf[nf][ks * 2], bf[nf][ks * 2 + 1]);
        }
        __syncthreads();
    }

#pragma unroll
    for (int nf = 0; nf < 4; nf++) {
        int m = m0 + wm * 16 + gid;
        int n = n0 + wn * 32 + nf * 8 + qid * 2;
        *(float2*)(out + (size_t)m * DIMM + n)       = make_float2(c[nf][0], c[nf][1]);
        *(float2*)(out + (size_t)(m + 8) * DIMM + n) = make_float2(c[nf][2], c[nf][3]);
    }
}

// ---------------------------------------------------------------------------
// fp16 HMMA cosformer attention: 32-row q-tiles, register-rotated key trig,
// 3-stage KV pipeline, fused normalize+gate epilogue. grid (32,8,2), 128 thr
// ---------------------------------------------------------------------------
#define APAD 72
#define AK_H   2304                  // K stages: 3 x 4608 halves
#define AV_H   16128                 // V stages: 3 x 4608 halves
#define ORED_B 4608                  // byte alias over K stages (epilogue only)
#define ATTN_SMEM_BYTES 59904

__global__ void __launch_bounds__(128) attn4_kernel()
{
    extern __shared__ __half asm_[];
    const uint32_t smb = smem_u32(asm_);
    __shared__ float zred[64];

    const int i = 31 - blockIdx.x;   // longest first
    const int h = blockIdx.y;
    const int b = blockIdx.z;
    const int tid = threadIdx.x;
    const int wid = tid >> 5;
    const int lane = tid & 31;
    const int gid = lane >> 2;
    const int qid = lane & 3;
    const int wm = wid & 1;          // 16-row half
    const int wn = wid >> 1;         // 32-col half

    const int jhi = (i >> 1) + 1;
    const int qrow0 = b * TSEQ + i * 32;
    const float ANG = (float)(3.14159265358979323846 / 2048.0);
    const float C64 = 0.99518472667219693f;   // cos(pi/32)
    const float S64 = 0.09801714032956060f;   // sin(pi/32)

    auto prefetch_kv = [&](int j, int s) {
#pragma unroll
        for (int t = 0; t < 4; t++) {
            int id = tid + t * 128;
            int row = id >> 3, seg = id & 7;
            uint32_t so = (uint32_t)(row * APAD + seg * 8) * 2;
            cp_async16(smb + (AK_H + s * 4608) * 2 + so,
                       g_Kx + (size_t)(b * TSEQ + j * 64 + row) * DIMM + h * DKH + seg * 8);
            cp_async16(smb + (AV_H + s * 4608) * 2 + so,
                       g_Vtx + (size_t)((b * 8 + h) * 64 + row) * TSEQ + j * 64 + seg * 8);
        }
    };

    // prologue: Q tile + KV chunk 0 in group 0; KV chunk 1 (or empty) in group 1
#pragma unroll
    for (int t = 0; t < 2; t++) {
        int id = tid + t * 128;
        int row = id >> 3, seg = id & 7;
        cp_async16(smb + (uint32_t)(row * APAD + seg * 8) * 2,
                   g_Qx + (size_t)(qrow0 + row) * DIMM + h * DKH + seg * 8);
    }
    prefetch_kv(0, 0);
    cp_commit();
    if (1 < jhi) prefetch_kv(1, 1);
    cp_commit();

    // query trig (fixed per thread)
    float cq0, sq0, cq1, sq1;
    {
        float a0 = (float)(i * 32 + wm * 16 + gid) * ANG;
        float a1 = (float)(i * 32 + wm * 16 + gid + 8) * ANG;
        sincosf(a0, &sq0, &cq0);
        sincosf(a1, &sq1, &cq1);
    }
    // key trig, register-resident, rotated by 64*ANG per j-step
    float ct[8], st[8];
#pragma unroll
    for (int nf = 0; nf < 4; nf++)
#pragma unroll
        for (int p = 0; p < 2; p++) {
            int cl = wn * 32 + nf * 8 + qid * 2 + p;
            sincosf((float)cl * ANG, &st[nf * 2 + p], &ct[nf * 2 + p]);
        }

    float oacc[8][4];
#pragma unroll
    for (int nf = 0; nf < 8; nf++)
#pragma unroll
        for (int k = 0; k < 4; k++) oacc[nf][k] = 0.f;
    float z0 = 0.f, z1 = 0.f;

    const uint32_t q_off = (uint32_t)((wm * 16 + (lane & 15)) * APAD + (lane >> 4) * 8) * 2;
    uint32_t qf[4][4];

    const int lr0 = i * 32 + wm * 16 + gid;   // global q rows
    const int lr1 = lr0 + 8;

    int stage = 0;
    for (int j = 0; j < jhi; j++) {
        cp_wait<1>();      // chunk j complete (prefetch distance 2)
        __syncthreads();
        if (j + 2 < jhi) {
            int ns = stage + 2; if (ns >= 3) ns -= 3;
            prefetch_kv(j + 2, ns);
        }
        cp_commit();       // uniform one-commit-per-iteration
        if (j == 0) {
#pragma unroll
            for (int ks = 0; ks < 4; ks++)
                ldsm4(qf[ks], smb + q_off + ks * 32);
        }

        const uint32_t Ks = smb + (AK_H + stage * 4608) * 2;
        const uint32_t Vs = smb + (AV_H + stage * 4608) * 2;

        // --- S = Q K^T (single pass) ---
        float sc[4][4];
#pragma unroll
        for (int nf = 0; nf < 4; nf++)
#pragma unroll
            for (int k = 0; k < 4; k++) sc[nf][k] = 0.f;

#pragma unroll
        for (int nf = 0; nf < 4; nf++) {
            const uint32_t ko = Ks + (uint32_t)((wn * 32 + nf * 8 + (lane & 7)) * APAD + (lane >> 3) * 8) * 2;
            uint32_t kf[8];
            ldsm4(kf, ko);
            ldsm4(kf + 4, ko + 64);
#pragma unroll
            for (int ks = 0; ks < 4; ks++)
                mma16816(sc[nf], qf[ks][0], qf[ks][1], qf[ks][2], qf[ks][3], kf[ks * 2], kf[ks * 2 + 1]);
        }

        // --- weight, mask, z, pack fp16 A-frags ---
        uint32_t af[2][4];
        const bool diag = (j == jhi - 1);
#pragma unroll
        for (int nf = 0; nf < 4; nf++) {
            const int cl0 = wn * 32 + nf * 8 + qid * 2;
            const int cg0 = j * 64 + cl0, cg1 = cg0 + 1;
            float ck0 = ct[nf * 2],     sk0 = st[nf * 2];
            float ck1 = ct[nf * 2 + 1], sk1 = st[nf * 2 + 1];
            float v0 = sc[nf][0] * (cq0 * ck0 + sq0 * sk0);
            float v1 = sc[nf][1] * (cq0 * ck1 + sq0 * sk1);
            float v2 = sc[nf][2] * (cq1 * ck0 + sq1 * sk0);
            float v3 = sc[nf][3] * (cq1 * ck1 + sq1 * sk1);
            if (diag) {
                if (cg0 > lr0) v0 = 0.f;
                if (cg1 > lr0) v1 = 0.f;
                if (cg0 > lr1) v2 = 0.f;
                if (cg1 > lr1) v3 = 0.f;
            }
            z0 += v0 + v1;
            z1 += v2 + v3;
            const int f = nf >> 1;
            if ((nf & 1) == 0) {
                af[f][0] = f22h2(v0, v1); af[f][1] = f22h2(v2, v3);
            } else {
                af[f][2] = f22h2(v0, v1); af[f][3] = f22h2(v2, v3);
            }
        }
        // rotate key trig by 64*ANG
#pragma unroll
        for (int p = 0; p < 8; p++) {
            float cn = ct[p] * C64 - st[p] * S64;
            st[p] = st[p] * C64 + ct[p] * S64;
            ct[p] = cn;
        }

        // --- O += S Vt^T (single pass) ---
#pragma unroll
        for (int nfv = 0; nfv < 8; nfv++) {
            const uint32_t vo = Vs + (uint32_t)((nfv * 8 + (lane & 7)) * APAD + wn * 32 + (lane >> 3) * 8) * 2;
            uint32_t vf[4];
            ldsm4(vf, vo);
#pragma unroll
            for (int f = 0; f < 2; f++)
                mma16816(oacc[nfv], af[f][0], af[f][1], af[f][2], af[f][3], vf[f * 2], vf[f * 2 + 1]);
        }

        if (++stage >= 3) stage = 0;
    }

    // quad-reduce z (cols within quad)
    z0 += __shfl_xor_sync(0xffffffffu, z0, 1);
    z0 += __shfl_xor_sync(0xffffffffu, z0, 2);
    z1 += __shfl_xor_sync(0xffffffffu, z1, 1);
    z1 += __shfl_xor_sync(0xffffffffu, z1, 2);

    __syncthreads();  // all warps done with K smem -> safe to alias Ored

    float* Ored = (float*)((char*)asm_ + ORED_B);    // [2][32][66]
    {
        const int r0 = wm * 16 + gid;
#pragma unroll
        for (int nfv = 0; nfv < 8; nfv++) {
            const int c = nfv * 8 + qid * 2;
            Ored[wn * 2112 + r0 * 66 + c]           = oacc[nfv][0];
            Ored[wn * 2112 + r0 * 66 + c + 1]       = oacc[nfv][1];
            Ored[wn * 2112 + (r0 + 8) * 66 + c]     = oacc[nfv][2];
            Ored[wn * 2112 + (r0 + 8) * 66 + c + 1] = oacc[nfv][3];
        }
        if (qid == 0) {
            zred[wn * 32 + r0]     = z0;
            zred[wn * 32 + r0 + 8] = z1;
        }
    }
    __syncthreads();

    // cooperative finish: normalize, gate, write single fp16 O
    {
        const int r = tid >> 2;
        const int cbase = (tid & 3) * 16;
        float z = zred[r] + zred[32 + r];
        float zinv = 1.f / fmaxf(z, 1e-6f);
        size_t gb = (size_t)(qrow0 + r) * DIMM + h * DKH + cbase;
#pragma unroll
        for (int p = 0; p < 8; p++) {
            const int c = cbase + p * 2;
            float va = Ored[r * 66 + c]     + Ored[2112 + r * 66 + c];
            float vb = Ored[r * 66 + c + 1] + Ored[2112 + r * 66 + c + 1];
            float2 g = *(const float2*)(g_G + gb + p * 2);
            va *= zinv * g.x;
            vb *= zinv * g.y;
            *(uint32_t*)(g_Ox + gb + p * 2) = f22h2(va, vb);
        }
    }
}

// ---------------------------------------------------------------------------
extern "C" void kernel_launch(void* const* d_in, const int* in_sizes, int n_in,
                              void* d_out, int out_size)
{
    const float* x  = (const float*)d_in[0];
    const float* Wq = (const float*)d_in[1];
    const float* Wk = (const float*)d_in[2];
    const float* Wv = (const float*)d_in[3];
    const float* Wo = (const float*)d_in[4];
    const float* Wg = (const float*)d_in[5];
    const float* bg = (const float*)d_in[6];

    cudaFuncSetAttribute(mma_proj_kernel, cudaFuncAttributeMaxDynamicSharedMemorySize, GEMM_SMEM_BYTES);
    cudaFuncSetAttribute(mma_out_kernel, cudaFuncAttributeMaxDynamicSharedMemorySize, GEMM_SMEM_BYTES);
    cudaFuncSetAttribute(attn4_kernel, cudaFuncAttributeMaxDynamicSharedMemorySize, ATTN_SMEM_BYTES);

    prep_kernel<<<dim3(16, 16, 9), 256>>>(x, Wq, Wk, Wv, Wg, Wo);
    mma_proj_kernel<<<dim3(4, 32, 4), 256, GEMM_SMEM_BYTES>>>(bg);
    attn4_kernel<<<dim3(32, 8, 2), 128, ATTN_SMEM_BYTES>>>();
    mma_out_kernel<<<dim3(4, 32), 512, GEMM_SMEM_BYTES>>>((float*)d_out);
}

// round 16
// speedup vs baseline: 1.0354x; 1.0354x over previous
#include <cuda_runtime.h>
#include <cuda_fp16.h>
#include <math.h>
#include <stdint.h>

// Problem constants
#define BATCH 2
#define TSEQ  1024
#define DIMM  512
#define NHEAD 8
#define DKH   64
#define NROWS (BATCH * TSEQ)   // 2048

// ---------------------------------------------------------------------------
// Scratch (__device__ globals) — everything single fp16
// ---------------------------------------------------------------------------
__device__ __align__(16) float  g_G[NROWS * DIMM];
__device__ __align__(16) __half g_Xh[NROWS * DIMM];     // x
__device__ __align__(16) __half g_Qx[NROWS * DIMM];     // Q
__device__ __align__(16) __half g_Kx[NROWS * DIMM];     // K
__device__ __align__(16) __half g_Vtx[NROWS * DIMM];    // V transposed [(b*8+h)*64+d][t]
__device__ __align__(16) __half g_Ox[NROWS * DIMM];     // gated O
__device__ __align__(16) __half g_Ws[5 * DIMM * DIMM];  // Wq,Wk,Wv,Wg,Wo ^T [n][k]

// ---------------------------------------------------------------------------
// helpers
// ---------------------------------------------------------------------------
__device__ __forceinline__ uint32_t smem_u32(const void* p) {
    uint32_t a;
    asm("{ .reg .u64 t; cvta.to.shared.u64 t, %1; cvt.u32.u64 %0, t; }" : "=r"(a) : "l"(p));
    return a;
}
__device__ __forceinline__ void cp_async16(uint32_t dst, const void* src) {
    asm volatile("cp.async.cg.shared.global [%0], [%1], 16;" :: "r"(dst), "l"(src));
}
__device__ __forceinline__ void cp_commit() {
    asm volatile("cp.async.commit_group;" ::: "memory");
}
template <int N>
__device__ __forceinline__ void cp_wait() {
    asm volatile("cp.async.wait_group %0;" :: "n"(N) : "memory");
}
__device__ __forceinline__ void ldsm4(uint32_t* r, uint32_t addr) {
    asm volatile("ldmatrix.sync.aligned.m8n8.x4.shared.b16 {%0,%1,%2,%3}, [%4];"
        : "=r"(r[0]), "=r"(r[1]), "=r"(r[2]), "=r"(r[3]) : "r"(addr));
}
__device__ __forceinline__ void mma16816(float* c,
                                         uint32_t a0, uint32_t a1, uint32_t a2, uint32_t a3,
                                         uint32_t b0, uint32_t b1) {
    asm volatile(
        "mma.sync.aligned.m16n8k16.row.col.f32.f16.f16.f32 "
        "{%0,%1,%2,%3}, {%4,%5,%6,%7}, {%8,%9}, {%0,%1,%2,%3};"
        : "+f"(c[0]), "+f"(c[1]), "+f"(c[2]), "+f"(c[3])
        : "r"(a0), "r"(a1), "r"(a2), "r"(a3), "r"(b0), "r"(b1));
}
__device__ __forceinline__ uint32_t f22h2(float a, float b) {
    __half2 t = __float22half2_rn(make_float2(a, b));
    return *(uint32_t*)&t;
}

// ---------------------------------------------------------------------------
// prep: z<5 -> weight transpose -> fp16 single; z>=5 -> x -> fp16
// ---------------------------------------------------------------------------
__global__ void __launch_bounds__(256) prep_kernel(
    const float* __restrict__ x,
    const float* __restrict__ Wq, const float* __restrict__ Wk,
    const float* __restrict__ Wv, const float* __restrict__ Wg,
    const float* __restrict__ Wo)
{
    if (blockIdx.z < 5) {
        __shared__ float t[32][33];
        const int w = blockIdx.z;
        const float* __restrict__ W = (w == 0) ? Wq : (w == 1) ? Wk : (w == 2) ? Wv : (w == 3) ? Wg : Wo;
        __half* Ws = g_Ws + (size_t)w * DIMM * DIMM;

        const int tx = threadIdx.x & 31, ty = threadIdx.x >> 5;
        const int n0 = blockIdx.x * 32, k0 = blockIdx.y * 32;
#pragma unroll
        for (int j = 0; j < 4; j++)
            t[ty + 8 * j][tx] = W[(size_t)(k0 + ty + 8 * j) * DIMM + n0 + tx];
        __syncthreads();
#pragma unroll
        for (int j = 0; j < 4; j++) {
            float v = t[tx][ty + 8 * j];
            size_t o = (size_t)(n0 + ty + 8 * j) * DIMM + k0 + tx;
            Ws[o] = __float2half(v);
        }
    } else {
        int bid = (blockIdx.z - 5) * 256 + blockIdx.y * 16 + blockIdx.x;
        int i4 = (bid * 256 + threadIdx.x) * 4;
        float4 v = *(const float4*)(x + i4);
        *(__half2*)(g_Xh + i4)     = __float22half2_rn(make_float2(v.x, v.y));
        *(__half2*)(g_Xh + i4 + 2) = __float22half2_rn(make_float2(v.z, v.w));
    }
}

// ---------------------------------------------------------------------------
// GEMM: 64x128 tile, K=512, chunk 32, 4-stage, 256 threads (R12 proven)
// MODE 0: float out; 2: transposed V single; 3: sigmoid+bias float; 4: relu single
// ---------------------------------------------------------------------------
#define PADK 40
#define BUFA_B (64 * PADK * 2)          // 5120 bytes
#define BUFB_B (128 * PADK * 2)         // 10240 bytes
#define STAGE_B (BUFA_B + BUFB_B)       // 15360
#define GEMM_SMEM_BYTES (4 * STAGE_B)   // 61440

template<int MODE>
__device__ __forceinline__ void gemm_tile(
    const __half* __restrict__ A0, const __half* __restrict__ B0,
    int m0, int n0,
    float* __restrict__ fout, __half* __restrict__ o1,
    const float* __restrict__ bias)
{
    extern __shared__ __half sm[];
    const uint32_t smb = smem_u32(sm);

    const int tid = threadIdx.x;
    const int wid = tid >> 5;
    const int lane = tid & 31;
    const int wm = wid >> 2;
    const int wn = wid & 3;
    const int gid = lane >> 2;
    const int qid = lane & 3;

    const uint32_t a_off = (uint32_t)((wm * 32 + (lane & 15)) * PADK + (lane >> 4) * 8) * 2;
    const uint32_t b_off = (uint32_t)((wn * 32 + (lane & 7)) * PADK + (lane >> 3) * 8) * 2;

    float c[2][4][4];
#pragma unroll
    for (int i = 0; i < 2; i++)
#pragma unroll
        for (int j = 0; j < 4; j++)
#pragma unroll
            for (int k = 0; k < 4; k++) c[i][j][k] = 0.f;

    auto prefetch = [&](int chunk, int stage) {
        const int k0 = chunk * 32;
        const uint32_t sbase = smb + (uint32_t)stage * STAGE_B;
        {
            int row = tid >> 2, seg = tid & 3;
            cp_async16(sbase + (uint32_t)(row * PADK + seg * 8) * 2,
                       A0 + (size_t)(m0 + row) * DIMM + k0 + seg * 8);
        }
#pragma unroll
        for (int t = 0; t < 2; t++) {
            int id = tid + t * 256;
            int row = id >> 2, seg = id & 3;
            cp_async16(sbase + BUFA_B + (uint32_t)(row * PADK + seg * 8) * 2,
                       B0 + (size_t)(n0 + row) * DIMM + k0 + seg * 8);
        }
        cp_commit();
    };

    prefetch(0, 0);
    prefetch(1, 1);
    prefetch(2, 2);

    for (int chunk = 0; chunk < 16; chunk++) {
        const int stage = chunk & 3;
        if (chunk + 3 < 16) prefetch(chunk + 3, (chunk + 3) & 3);
        else cp_commit();
        cp_wait<3>();
        __syncthreads();

        const uint32_t s0 = smb + (uint32_t)stage * STAGE_B;

        uint32_t bf[4][4];
#pragma unroll
        for (int nf = 0; nf < 4; nf++)
            ldsm4(bf[nf], s0 + BUFA_B + b_off + (uint32_t)nf * (8 * PADK * 2));

#pragma unroll
        for (int ks = 0; ks < 2; ks++) {
            uint32_t af[2][4];
#pragma unroll
            for (int mf = 0; mf < 2; mf++)
                ldsm4(af[mf], s0 + a_off + (uint32_t)mf * (16 * PADK * 2) + (uint32_t)ks * 32);
#pragma unroll
            for (int nf = 0; nf < 4; nf++) {
                const uint32_t p0 = bf[nf][ks * 2], p1 = bf[nf][ks * 2 + 1];
#pragma unroll
                for (int mf = 0; mf < 2; mf++)
                    mma16816(c[mf][nf], af[mf][0], af[mf][1], af[mf][2], af[mf][3], p0, p1);
            }
        }
        __syncthreads();
    }

#pragma unroll
    for (int mf = 0; mf < 2; mf++) {
#pragma unroll
        for (int nf = 0; nf < 4; nf++) {
            int m = m0 + wm * 32 + mf * 16 + gid;
            int n = n0 + wn * 32 + nf * 8 + qid * 2;
            float v0 = c[mf][nf][0], v1 = c[mf][nf][1];
            float v2 = c[mf][nf][2], v3 = c[mf][nf][3];
            if (MODE == 0) {
                *(float2*)(fout + (size_t)m * DIMM + n)       = make_float2(v0, v1);
                *(float2*)(fout + (size_t)(m + 8) * DIMM + n) = make_float2(v2, v3);
            } else if (MODE == 2) {
                int bb = m >> 10, tt = m & 1023;
                int hh = n >> 6, dd = n & 63;
                size_t base = ((size_t)((bb * 8 + hh) * 64 + dd)) * 1024 + tt;
                o1[base]        = __float2half(v0);
                o1[base + 1024] = __float2half(v1);
                o1[base + 8]    = __float2half(v2);
                o1[base + 1032] = __float2half(v3);
            } else if (MODE == 3) {
                float b0 = bias[n], b1v = bias[n + 1];
                v0 = 1.f / (1.f + expf(-(v0 + b0)));
                v1 = 1.f / (1.f + expf(-(v1 + b1v)));
                v2 = 1.f / (1.f + expf(-(v2 + b0)));
                v3 = 1.f / (1.f + expf(-(v3 + b1v)));
                *(float2*)(fout + (size_t)m * DIMM + n)       = make_float2(v0, v1);
                *(float2*)(fout + (size_t)(m + 8) * DIMM + n) = make_float2(v2, v3);
            } else { // MODE 4: relu -> single fp16
                v0 = fmaxf(v0, 0.f); v1 = fmaxf(v1, 0.f);
                v2 = fmaxf(v2, 0.f); v3 = fmaxf(v3, 0.f);
                *(uint32_t*)(o1 + (size_t)m * DIMM + n)       = f22h2(v0, v1);
                *(uint32_t*)(o1 + (size_t)(m + 8) * DIMM + n) = f22h2(v2, v3);
            }
        }
    }
}

__global__ void __launch_bounds__(256) mma_proj_kernel(const float* __restrict__ bg)
{
    const int zi = blockIdx.z;
    const int m0 = blockIdx.y * 64, n0 = blockIdx.x * 128;
    if (zi == 0)
        gemm_tile<4>(g_Xh, g_Ws + 0 * DIMM * DIMM, m0, n0, nullptr, g_Qx, nullptr);
    else if (zi == 1)
        gemm_tile<4>(g_Xh, g_Ws + 1 * DIMM * DIMM, m0, n0, nullptr, g_Kx, nullptr);
    else if (zi == 2)
        gemm_tile<2>(g_Xh, g_Ws + 2 * DIMM * DIMM, m0, n0, nullptr, g_Vtx, nullptr);
    else
        gemm_tile<3>(g_Xh, g_Ws + 3 * DIMM * DIMM, m0, n0, g_G, nullptr, bg);
}

__global__ void __launch_bounds__(256) mma_out_kernel(float* __restrict__ out)
{
    gemm_tile<0>(g_Ox, g_Ws + 4 * DIMM * DIMM,
                 blockIdx.y * 64, blockIdx.x * 128, out, nullptr, nullptr);
}

// ---------------------------------------------------------------------------
// fp16 HMMA cosformer attention: 32-row q-tiles, register-rotated key trig,
// 2-stage KV double buffering (41.5KB smem -> 5 CTAs/SM), fused epilogue.
// grid (32,8,2), 128 threads
// ---------------------------------------------------------------------------
#define APAD 72
#define AK_H   2304                  // K stages: 2 x 4608 halves
#define AV_H   11520                 // V stages: 2 x 4608 halves
#define ORED_B 4608                  // byte alias over K stages (epilogue only)
#define ATTN_SMEM_BYTES 41472

__global__ void __launch_bounds__(128) attn4_kernel()
{
    extern __shared__ __half asm_[];
    const uint32_t smb = smem_u32(asm_);
    __shared__ float zred[64];

    const int i = 31 - blockIdx.x;   // longest first
    const int h = blockIdx.y;
    const int b = blockIdx.z;
    const int tid = threadIdx.x;
    const int wid = tid >> 5;
    const int lane = tid & 31;
    const int gid = lane >> 2;
    const int qid = lane & 3;
    const int wm = wid & 1;          // 16-row half
    const int wn = wid >> 1;         // 32-col half

    const int jhi = (i >> 1) + 1;
    const int qrow0 = b * TSEQ + i * 32;
    const float ANG = (float)(3.14159265358979323846 / 2048.0);
    const float C64 = 0.99518472667219693f;   // cos(pi/32)
    const float S64 = 0.09801714032956060f;   // sin(pi/32)

    auto prefetch_kv = [&](int j, int s) {
#pragma unroll
        for (int t = 0; t < 4; t++) {
            int id = tid + t * 128;
            int row = id >> 3, seg = id & 7;
            uint32_t so = (uint32_t)(row * APAD + seg * 8) * 2;
            cp_async16(smb + (AK_H + s * 4608) * 2 + so,
                       g_Kx + (size_t)(b * TSEQ + j * 64 + row) * DIMM + h * DKH + seg * 8);
            cp_async16(smb + (AV_H + s * 4608) * 2 + so,
                       g_Vtx + (size_t)((b * 8 + h) * 64 + row) * TSEQ + j * 64 + seg * 8);
        }
    };

    // prologue: Q tile + KV chunk 0
#pragma unroll
    for (int t = 0; t < 2; t++) {
        int id = tid + t * 128;
        int row = id >> 3, seg = id & 7;
        cp_async16(smb + (uint32_t)(row * APAD + seg * 8) * 2,
                   g_Qx + (size_t)(qrow0 + row) * DIMM + h * DKH + seg * 8);
    }
    prefetch_kv(0, 0);
    cp_commit();

    // query trig (fixed per thread)
    float cq0, sq0, cq1, sq1;
    {
        float a0 = (float)(i * 32 + wm * 16 + gid) * ANG;
        float a1 = (float)(i * 32 + wm * 16 + gid + 8) * ANG;
        sincosf(a0, &sq0, &cq0);
        sincosf(a1, &sq1, &cq1);
    }
    // key trig, register-resident, rotated by 64*ANG per j-step
    float ct[8], st[8];
#pragma unroll
    for (int nf = 0; nf < 4; nf++)
#pragma unroll
        for (int p = 0; p < 2; p++) {
            int cl = wn * 32 + nf * 8 + qid * 2 + p;
            sincosf((float)cl * ANG, &st[nf * 2 + p], &ct[nf * 2 + p]);
        }

    float oacc[8][4];
#pragma unroll
    for (int nf = 0; nf < 8; nf++)
#pragma unroll
        for (int k = 0; k < 4; k++) oacc[nf][k] = 0.f;
    float z0 = 0.f, z1 = 0.f;

    const uint32_t q_off = (uint32_t)((wm * 16 + (lane & 15)) * APAD + (lane >> 4) * 8) * 2;
    uint32_t qf[4][4];

    const int lr0 = i * 32 + wm * 16 + gid;   // global q rows
    const int lr1 = lr0 + 8;

    for (int j = 0; j < jhi; j++) {
        const int s = j & 1;
        cp_wait<0>();
        __syncthreads();
        if (j + 1 < jhi) prefetch_kv(j + 1, s ^ 1);
        cp_commit();
        if (j == 0) {
#pragma unroll
            for (int ks = 0; ks < 4; ks++)
                ldsm4(qf[ks], smb + q_off + ks * 32);
        }

        const uint32_t Ks = smb + (AK_H + s * 4608) * 2;
        const uint32_t Vs = smb + (AV_H + s * 4608) * 2;

        // --- S = Q K^T (single pass) ---
        float sc[4][4];
#pragma unroll
        for (int nf = 0; nf < 4; nf++)
#pragma unroll
            for (int k = 0; k < 4; k++) sc[nf][k] = 0.f;

#pragma unroll
        for (int nf = 0; nf < 4; nf++) {
            const uint32_t ko = Ks + (uint32_t)((wn * 32 + nf * 8 + (lane & 7)) * APAD + (lane >> 3) * 8) * 2;
            uint32_t kf[8];
            ldsm4(kf, ko);
            ldsm4(kf + 4, ko + 64);
#pragma unroll
            for (int ks = 0; ks < 4; ks++)
                mma16816(sc[nf], qf[ks][0], qf[ks][1], qf[ks][2], qf[ks][3], kf[ks * 2], kf[ks * 2 + 1]);
        }

        // --- weight, mask, z, pack fp16 A-frags ---
        uint32_t af[2][4];
        const bool diag = (j == jhi - 1);
#pragma unroll
        for (int nf = 0; nf < 4; nf++) {
            const int cl0 = wn * 32 + nf * 8 + qid * 2;
            const int cg0 = j * 64 + cl0, cg1 = cg0 + 1;
            float ck0 = ct[nf * 2],     sk0 = st[nf * 2];
            float ck1 = ct[nf * 2 + 1], sk1 = st[nf * 2 + 1];
            float v0 = sc[nf][0] * (cq0 * ck0 + sq0 * sk0);
            float v1 = sc[nf][1] * (cq0 * ck1 + sq0 * sk1);
            float v2 = sc[nf][2] * (cq1 * ck0 + sq1 * sk0);
            float v3 = sc[nf][3] * (cq1 * ck1 + sq1 * sk1);
            if (diag) {
                if (cg0 > lr0) v0 = 0.f;
                if (cg1 > lr0) v1 = 0.f;
                if (cg0 > lr1) v2 = 0.f;
                if (cg1 > lr1) v3 = 0.f;
            }
            z0 += v0 + v1;
            z1 += v2 + v3;
            const int f = nf >> 1;
            if ((nf & 1) == 0) {
                af[f][0] = f22h2(v0, v1); af[f][1] = f22h2(v2, v3);
            } else {
                af[f][2] = f22h2(v0, v1); af[f][3] = f22h2(v2, v3);
            }
        }
        // rotate key trig by 64*ANG
#pragma unroll
        for (int p = 0; p < 8; p++) {
            float cn = ct[p] * C64 - st[p] * S64;
            st[p] = st[p] * C64 + ct[p] * S64;
            ct[p] = cn;
        }

        // --- O += S Vt^T (single pass) ---
#pragma unroll
        for (int nfv = 0; nfv < 8; nfv++) {
            const uint32_t vo = Vs + (uint32_t)((nfv * 8 + (lane & 7)) * APAD + wn * 32 + (lane >> 3) * 8) * 2;
            uint32_t vf[4];
            ldsm4(vf, vo);
#pragma unroll
            for (int f = 0; f < 2; f++)
                mma16816(oacc[nfv], af[f][0], af[f][1], af[f][2], af[f][3], vf[f * 2], vf[f * 2 + 1]);
        }
    }

    // quad-reduce z (cols within quad)
    z0 += __shfl_xor_sync(0xffffffffu, z0, 1);
    z0 += __shfl_xor_sync(0xffffffffu, z0, 2);
    z1 += __shfl_xor_sync(0xffffffffu, z1, 1);
    z1 += __shfl_xor_sync(0xffffffffu, z1, 2);

    __syncthreads();  // all warps done with K smem -> safe to alias Ored

    float* Ored = (float*)((char*)asm_ + ORED_B);    // [2][32][66]
    {
        const int r0 = wm * 16 + gid;
#pragma unroll
        for (int nfv = 0; nfv < 8; nfv++) {
            const int c = nfv * 8 + qid * 2;
            Ored[wn * 2112 + r0 * 66 + c]           = oacc[nfv][0];
            Ored[wn * 2112 + r0 * 66 + c + 1]       = oacc[nfv][1];
            Ored[wn * 2112 + (r0 + 8) * 66 + c]     = oacc[nfv][2];
            Ored[wn * 2112 + (r0 + 8) * 66 + c + 1] = oacc[nfv][3];
        }
        if (qid == 0) {
            zred[wn * 32 + r0]     = z0;
            zred[wn * 32 + r0 + 8] = z1;
        }
    }
    __syncthreads();

    // cooperative finish: normalize, gate, write single fp16 O
    {
        const int r = tid >> 2;
        const int cbase = (tid & 3) * 16;
        float z = zred[r] + zred[32 + r];
        float zinv = 1.f / fmaxf(z, 1e-6f);
        size_t gb = (size_t)(qrow0 + r) * DIMM + h * DKH + cbase;
#pragma unroll
        for (int p = 0; p < 8; p++) {
            const int c = cbase + p * 2;
            float va = Ored[r * 66 + c]     + Ored[2112 + r * 66 + c];
            float vb = Ored[r * 66 + c + 1] + Ored[2112 + r * 66 + c + 1];
            float2 g = *(const float2*)(g_G + gb + p * 2);
            va *= zinv * g.x;
            vb *= zinv * g.y;
            *(uint32_t*)(g_Ox + gb + p * 2) = f22h2(va, vb);
        }
    }
}

// ---------------------------------------------------------------------------
extern "C" void kernel_launch(void* const* d_in, const int* in_sizes, int n_in,
                              void* d_out, int out_size)
{
    const float* x  = (const float*)d_in[0];
    const float* Wq = (const float*)d_in[1];
    const float* Wk = (const float*)d_in[2];
    const float* Wv = (const float*)d_in[3];
    const float* Wo = (const float*)d_in[4];
    const float* Wg = (const float*)d_in[5];
    const float* bg = (const float*)d_in[6];

    cudaFuncSetAttribute(mma_proj_kernel, cudaFuncAttributeMaxDynamicSharedMemorySize, GEMM_SMEM_BYTES);
    cudaFuncSetAttribute(mma_out_kernel, cudaFuncAttributeMaxDynamicSharedMemorySize, GEMM_SMEM_BYTES);
    cudaFuncSetAttribute(attn4_kernel, cudaFuncAttributeMaxDynamicSharedMemorySize, ATTN_SMEM_BYTES);

    prep_kernel<<<dim3(16, 16, 9), 256>>>(x, Wq, Wk, Wv, Wg, Wo);
    mma_proj_kernel<<<dim3(4, 32, 4), 256, GEMM_SMEM_BYTES>>>(bg);
    attn4_kernel<<<dim3(32, 8, 2), 128, ATTN_SMEM_BYTES>>>();
    mma_out_kernel<<<dim3(4, 32), 256, GEMM_SMEM_BYTES>>>((float*)d_out);
}